// round 16
// baseline (speedup 1.0000x reference)
#include <cuda_runtime.h>
#include <cuda_bf16.h>
#include <math.h>
#include <stdint.h>

// NT-Xent loss. B=4096, D=512. Symmetric fused bf16 HMMA sim-GEMM (R15
// denom). Normalize split 64-threads-per-pair for occupancy; diag tiles
// skip col-sum finalize.

#define D 512
#define MAXN 8192
#define TEMP_INV 2.0f
#define QSCALE 1.6986436f   // sqrt(2 * log2(e))
#define NCTA 148
#define NB 64
#define NTILES 2080

#define TM 128
#define KCHUNK 128

#define SA_OFF 0
#define SA_BYTES (TM * D * 2)
#define SB_OFF SA_BYTES
#define SB_BYTES (TM * KCHUNK * 2)
#define NSTAGE 3
#define SRED_OFF (SB_OFF + NSTAGE * SB_BYTES)
#define SMEM_TOTAL (SRED_OFF + 2048)

#define NLBLK 1024
#define NZR (NB * 33 * 128)

__device__ __nv_bfloat16 g_znb[(size_t)MAXN * D];
__device__ float g_pos[MAXN / 2];
__device__ float g_diag[MAXN];      // |q_row|^2 (exp2 arg of the diagonal)
__device__ float g_rs[NZR];
__device__ float g_cs[NZR];
__device__ float g_bpart[NLBLK];
__device__ unsigned int g_ctr = 0;

__device__ __forceinline__ uint32_t smem_u32(const void* p) {
    uint32_t a;
    asm("{ .reg .u64 t; cvta.to.shared.u64 t, %1; cvt.u32.u64 %0, t; }" : "=r"(a) : "l"(p));
    return a;
}
__device__ __forceinline__ float ex2f(float x) {
    float r;
    asm("ex2.approx.f32 %0, %1;" : "=f"(r) : "f"(x));
    return r;
}
__device__ __forceinline__ void ldsm4(uint32_t* r, uint32_t addr) {
    asm volatile("ldmatrix.sync.aligned.m8n8.x4.shared.b16 {%0,%1,%2,%3}, [%4];"
                 : "=r"(r[0]), "=r"(r[1]), "=r"(r[2]), "=r"(r[3]) : "r"(addr));
}
__device__ __forceinline__ void mma_bf16(float* c, const uint32_t* a, const uint32_t* b) {
    asm volatile(
        "mma.sync.aligned.m16n8k16.row.col.f32.bf16.bf16.f32 "
        "{%0,%1,%2,%3}, {%4,%5,%6,%7}, {%8,%9}, {%0,%1,%2,%3};"
        : "+f"(c[0]), "+f"(c[1]), "+f"(c[2]), "+f"(c[3])
        : "r"(a[0]), "r"(a[1]), "r"(a[2]), "r"(a[3]), "r"(b[0]), "r"(b[1]));
}
__device__ __forceinline__ void tmap(int t, int& r, int& off, int& c) {
    if (t < 32 * 33) { r = t / 33; off = t - r * 33; }
    else { int u = t - 32 * 33; r = 32 + u / 32; off = u - (u / 32) * 32; }
    c = (r + off) & 63;
}

// ---------------------------------------------------------------------------
// 1) normalize: 64 threads per pair (2 warps), 4 pairs per 256-thread block.
// ---------------------------------------------------------------------------
__global__ void normalize_kernel(const float* __restrict__ zi,
                                 const float* __restrict__ zj, int B) {
    int tid = threadIdx.x;
    int p = tid >> 6;         // pair within block (0..3)
    int sub = tid & 63;       // thread within pair
    int lane = tid & 31;
    int w = tid >> 5;         // warp in block (0..7); pair p spans warps 2p, 2p+1
    int row = blockIdx.x * 4 + p;

    const float4* pi = (const float4*)(zi + (size_t)row * D);
    const float4* pj = (const float4*)(zj + (size_t)row * D);
    float4 vi0 = pi[sub * 2], vi1 = pi[sub * 2 + 1];
    float4 vj0 = pj[sub * 2], vj1 = pj[sub * 2 + 1];

    float ssi = vi0.x * vi0.x + vi0.y * vi0.y + vi0.z * vi0.z + vi0.w * vi0.w
              + vi1.x * vi1.x + vi1.y * vi1.y + vi1.z * vi1.z + vi1.w * vi1.w;
    float ssj = vj0.x * vj0.x + vj0.y * vj0.y + vj0.z * vj0.z + vj0.w * vj0.w
              + vj1.x * vj1.x + vj1.y * vj1.y + vj1.z * vj1.z + vj1.w * vj1.w;
    float dij = vi0.x * vj0.x + vi0.y * vj0.y + vi0.z * vj0.z + vi0.w * vj0.w
              + vi1.x * vj1.x + vi1.y * vj1.y + vi1.z * vj1.z + vi1.w * vj1.w;
#pragma unroll
    for (int o = 16; o > 0; o >>= 1) {
        ssi += __shfl_xor_sync(0xffffffffu, ssi, o);
        ssj += __shfl_xor_sync(0xffffffffu, ssj, o);
        dij += __shfl_xor_sync(0xffffffffu, dij, o);
    }
    __shared__ float s3[8][3];
    __shared__ float s2[8][2];
    if (lane == 0) { s3[w][0] = ssi; s3[w][1] = ssj; s3[w][2] = dij; }
    __syncthreads();
    ssi = s3[p * 2][0] + s3[p * 2 + 1][0];
    ssj = s3[p * 2][1] + s3[p * 2 + 1][1];
    dij = s3[p * 2][2] + s3[p * 2 + 1][2];

    float ri = rsqrtf(ssi), rj = rsqrtf(ssj);
    float sci = ri * QSCALE, scj = rj * QSCALE;

    __nv_bfloat16* oi = g_znb + (size_t)row * D + sub * 8;
    __nv_bfloat16* oj = g_znb + (size_t)(row + B) * D + sub * 8;
    __nv_bfloat162 a0 = __floats2bfloat162_rn(vi0.x * sci, vi0.y * sci);
    __nv_bfloat162 a1 = __floats2bfloat162_rn(vi0.z * sci, vi0.w * sci);
    __nv_bfloat162 a2 = __floats2bfloat162_rn(vi1.x * sci, vi1.y * sci);
    __nv_bfloat162 a3 = __floats2bfloat162_rn(vi1.z * sci, vi1.w * sci);
    *(__nv_bfloat162*)(oi) = a0;
    *(__nv_bfloat162*)(oi + 2) = a1;
    *(__nv_bfloat162*)(oi + 4) = a2;
    *(__nv_bfloat162*)(oi + 6) = a3;
    __nv_bfloat162 b0 = __floats2bfloat162_rn(vj0.x * scj, vj0.y * scj);
    __nv_bfloat162 b1 = __floats2bfloat162_rn(vj0.z * scj, vj0.w * scj);
    __nv_bfloat162 b2 = __floats2bfloat162_rn(vj1.x * scj, vj1.y * scj);
    __nv_bfloat162 b3 = __floats2bfloat162_rn(vj1.z * scj, vj1.w * scj);
    *(__nv_bfloat162*)(oj) = b0;
    *(__nv_bfloat162*)(oj + 2) = b1;
    *(__nv_bfloat162*)(oj + 4) = b2;
    *(__nv_bfloat162*)(oj + 6) = b3;

    // |q|^2 of quantized rows for diagonal subtraction
    float qsi = 0.f, qsj = 0.f;
    float2 f;
    f = __bfloat1622float2(a0); qsi += f.x * f.x + f.y * f.y;
    f = __bfloat1622float2(a1); qsi += f.x * f.x + f.y * f.y;
    f = __bfloat1622float2(a2); qsi += f.x * f.x + f.y * f.y;
    f = __bfloat1622float2(a3); qsi += f.x * f.x + f.y * f.y;
    f = __bfloat1622float2(b0); qsj += f.x * f.x + f.y * f.y;
    f = __bfloat1622float2(b1); qsj += f.x * f.x + f.y * f.y;
    f = __bfloat1622float2(b2); qsj += f.x * f.x + f.y * f.y;
    f = __bfloat1622float2(b3); qsj += f.x * f.x + f.y * f.y;
#pragma unroll
    for (int o = 16; o > 0; o >>= 1) {
        qsi += __shfl_xor_sync(0xffffffffu, qsi, o);
        qsj += __shfl_xor_sync(0xffffffffu, qsj, o);
    }
    if (lane == 0) { s2[w][0] = qsi; s2[w][1] = qsj; }
    __syncthreads();
    if (sub == 0) {
        g_pos[row] = dij * ri * rj * TEMP_INV;
        g_diag[row] = s2[p * 2][0] + s2[p * 2 + 1][0];
        g_diag[row + B] = s2[p * 2][1] + s2[p * 2 + 1][1];
    }
    for (int i = blockIdx.x * blockDim.x + tid; i < NZR; i += gridDim.x * blockDim.x)
        g_rs[i] = 0.0f;
}

// ---------------------------------------------------------------------------
// 2) denom helpers (R15)
// ---------------------------------------------------------------------------
__device__ __forceinline__ void prefetchB(const __nv_bfloat16* __restrict__ znb,
                                          int colBase, int kc, uint32_t smemBuf, int tid) {
#pragma unroll
    for (int i = 0; i < 8; i++) {
        int idx = tid + i * 256;
        int n = idx >> 4;
        int c = idx & 15;
        const void* g = znb + (size_t)(colBase + n) * D + kc * KCHUNK + c * 8;
        uint32_t s = smemBuf + n * 256 + ((c ^ (n & 7)) << 4);
        asm volatile("cp.async.cg.shared.global [%0], [%1], 16;" :: "r"(s), "l"(g));
    }
    asm volatile("cp.async.commit_group;");
}
__device__ __forceinline__ void loadA(const __nv_bfloat16* __restrict__ znb,
                                      int rowBase, uint32_t sA, int tid) {
#pragma unroll 8
    for (int idx = tid; idx < TM * 64; idx += 256) {
        int r = idx >> 6;
        int c = idx & 63;
        const void* g = znb + (size_t)(rowBase + r) * D + c * 8;
        uint32_t s = sA + r * 1024 + ((c ^ (r & 7)) << 4);
        asm volatile("cp.async.cg.shared.global [%0], [%1], 16;" :: "r"(s), "l"(g));
    }
    asm volatile("cp.async.commit_group;");
}

__device__ __forceinline__ void emit_rows(float rowp[2][2], int r, int offFirst,
                                          float* scratch, int tid, int lane,
                                          int warpM, int warpN) {
    __syncthreads();
#pragma unroll
    for (int mt = 0; mt < 2; mt++)
#pragma unroll
        for (int h = 0; h < 2; h++) {
            float p = rowp[mt][h];
            p += __shfl_xor_sync(0xffffffffu, p, 1);
            p += __shfl_xor_sync(0xffffffffu, p, 2);
            rowp[mt][h] = p;
        }
    if ((lane & 3) == 0) {
#pragma unroll
        for (int mt = 0; mt < 2; mt++)
#pragma unroll
            for (int h = 0; h < 2; h++) {
                int rl = warpM * 32 + mt * 16 + (lane >> 2) + 8 * h;
                scratch[rl * 2 + warpN] = rowp[mt][h];
            }
    }
    __syncthreads();
    if (tid < TM)
        g_rs[(r * 33 + offFirst) * 128 + tid] = scratch[tid * 2] + scratch[tid * 2 + 1];
}

// uniform epilogue: 4 groups [g0, g0+4) -> row + col partials (no diag mask)
__device__ __forceinline__ void stale_groups(int g0, float (&st)[2][8][4],
                                             float (&rowp)[2][2], float (&colp)[8][2]) {
#pragma unroll
    for (int u = 0; u < 4; u++) {
        const int g = g0 + u;
        const int mt = g >> 3, nt = g & 7;
        float e0 = ex2f(st[mt][nt][0]);
        float e1 = ex2f(st[mt][nt][1]);
        float e2 = ex2f(st[mt][nt][2]);
        float e3 = ex2f(st[mt][nt][3]);
        rowp[mt][0] += e0 + e1;
        rowp[mt][1] += e2 + e3;
        colp[nt][0] += e0 + e2;
        colp[nt][1] += e1 + e3;
        st[mt][nt][0] = 0.f; st[mt][nt][1] = 0.f;
        st[mt][nt][2] = 0.f; st[mt][nt][3] = 0.f;
    }
}

__device__ __forceinline__ void colp_reset(float (&colp)[8][2]) {
#pragma unroll
    for (int nt = 0; nt < 8; nt++) { colp[nt][0] = 0.f; colp[nt][1] = 0.f; }
}

__device__ __forceinline__ void colp_finalize(float (&colp)[8][2], int staleR, int staleOff,
                                              float* scratch, int tid, int lane,
                                              int warpM, int warpN) {
    __syncthreads();
#pragma unroll
    for (int nt = 0; nt < 8; nt++)
#pragma unroll
        for (int q = 0; q < 2; q++) {
            float p = colp[nt][q];
            p += __shfl_xor_sync(0xffffffffu, p, 4);
            p += __shfl_xor_sync(0xffffffffu, p, 8);
            p += __shfl_xor_sync(0xffffffffu, p, 16);
            colp[nt][q] = p;
        }
    if (lane < 4) {
#pragma unroll
        for (int nt = 0; nt < 8; nt++)
#pragma unroll
            for (int q = 0; q < 2; q++)
                scratch[(warpN * 4 + warpM) * 64 + nt * 8 + lane * 2 + q] = colp[nt][q];
    }
    __syncthreads();
    if (tid < TM) {
        int wn = tid >> 6, cl = tid & 63;
        float s = scratch[(wn * 4 + 0) * 64 + cl] + scratch[(wn * 4 + 1) * 64 + cl]
                + scratch[(wn * 4 + 2) * 64 + cl] + scratch[(wn * 4 + 3) * 64 + cl];
        g_cs[(staleR * 33 + staleOff) * 128 + tid] = s;
    }
    colp_reset(colp);
}

__device__ __forceinline__ void flush_stale(float (&st)[2][8][4], float (&rowp)[2][2],
                                            float (&colp)[8][2], int staleOff, int staleR,
                                            float* scratch, int tid, int lane,
                                            int warpM, int warpN) {
    stale_groups(0, st, rowp, colp);
    stale_groups(4, st, rowp, colp);
    stale_groups(8, st, rowp, colp);
    stale_groups(12, st, rowp, colp);
    if (staleOff > 0)
        colp_finalize(colp, staleR, staleOff, scratch, tid, lane, warpM, warpN);
    else
        colp_reset(colp);   // diag tile col sums unused
}

// one tile (R11 scheduling): 4 kc MMA blocks into cur, each followed by a
// quarter of the stale epilogue
__device__ __forceinline__ void tile_body(
    float (&cur)[2][8][4], float (&st)[2][8][4],
    float (&rowp)[2][2], float (&colp)[8][2],
    int tIdx, int istart, int nIts, int haveStale,
    const __nv_bfloat16* __restrict__ znb,
    uint32_t sB, uint32_t aBase, int aXor, int aC,
    int bRow, int bXor, int bC, int tid)
{
#pragma unroll
    for (int kc = 0; kc < 4; ++kc) {
        const int git = (tIdx - istart) * 4 + kc;
        asm volatile("cp.async.wait_group 1;");
        __syncthreads();
        if (git + 2 < nIts) {
            int r2, o2, c2;
            tmap(istart + ((git + 2) >> 2), r2, o2, c2);
            prefetchB(znb, c2 * TM, (git + 2) & 3, sB + ((git + 2) % 3) * SB_BYTES, tid);
        } else {
            asm volatile("cp.async.commit_group;");
        }
        const uint32_t bufB = sB + (git % 3) * SB_BYTES;
#pragma unroll
        for (int s = 0; s < 8; ++s) {
            uint32_t af[2][4];
#pragma unroll
            for (int mt = 0; mt < 2; mt++)
                ldsm4(af[mt], aBase + mt * 16384 + (((kc * 16 + s * 2 + aC) ^ aXor) << 4));
#pragma unroll
            for (int bg = 0; bg < 4; bg++) {
                uint32_t bf[4];
                ldsm4(bf, bufB + (bRow + bg * 16) * 256 + (((s * 2 + bC) ^ bXor) << 4));
#pragma unroll
                for (int mt = 0; mt < 2; mt++) {
                    mma_bf16(cur[mt][bg * 2], af[mt], bf);
                    mma_bf16(cur[mt][bg * 2 + 1], af[mt], bf + 2);
                }
            }
        }
        if (haveStale)
            stale_groups(kc * 4, st, rowp, colp);
    }
}

__global__ void __launch_bounds__(256, 1) denom_kernel() {
    extern __shared__ char smem[];
    const int tid = threadIdx.x;
    const int lane = tid & 31;
    const int wid = tid >> 5;
    const int warpM = wid & 3;
    const int warpN = wid >> 2;
    const int cta = blockIdx.x;

    const __nv_bfloat16* __restrict__ znb = g_znb;
    uint32_t sA = smem_u32(smem) + SA_OFF;
    uint32_t sB = smem_u32(smem) + SB_OFF;
    float* scratch = (float*)(smem + SRED_OFF);

    const int aRow = warpM * 32 + (lane & 15);
    const uint32_t aBase = sA + aRow * 1024;
    const int aXor = aRow & 7;
    const int aC = lane >> 4;
    const int bRow = warpN * 64 + (lane & 7) + ((lane >> 4) << 3);
    const int bXor = bRow & 7;
    const int bC = (lane >> 3) & 1;

    const int istart = (cta * NTILES) / NCTA;
    const int iend = ((cta + 1) * NTILES) / NCTA;
    const int nIts = (iend - istart) * 4;

    int rcur, offcur, ccur;
    tmap(istart, rcur, offcur, ccur);
    int rprev = rcur;
    int offFirst = offcur;

    loadA(znb, rcur * TM, sA, tid);
    asm volatile("cp.async.wait_group 0;");
    __syncthreads();
    prefetchB(znb, ccur * TM, 0, sB, tid);
    prefetchB(znb, ccur * TM, 1, sB + SB_BYTES, tid);

    float accA[2][8][4], accB[2][8][4];
#pragma unroll
    for (int mt = 0; mt < 2; mt++)
#pragma unroll
        for (int nt = 0; nt < 8; nt++)
#pragma unroll
            for (int j = 0; j < 4; j++) { accA[mt][nt][j] = 0.f; accB[mt][nt][j] = 0.f; }
    float rowp[2][2] = {{0.f, 0.f}, {0.f, 0.f}};
    float colp[8][2];
    colp_reset(colp);

    int staleOff = -1, staleR = 0;

    for (int t = istart; t < iend; ++t) {
        tmap(t, rcur, offcur, ccur);
        const int par = (t - istart) & 1;
        if (rcur != rprev) {
            if (staleOff >= 0) {
                if (par == 0)
                    flush_stale(accB, rowp, colp, staleOff, staleR, scratch, tid, lane, warpM, warpN);
                else
                    flush_stale(accA, rowp, colp, staleOff, staleR, scratch, tid, lane, warpM, warpN);
                staleOff = -1;
            }
            emit_rows(rowp, rprev, offFirst, scratch, tid, lane, warpM, warpN);
            rowp[0][0] = rowp[0][1] = rowp[1][0] = rowp[1][1] = 0.f;
            offFirst = offcur;
            asm volatile("cp.async.wait_group 0;");
            __syncthreads();
            loadA(znb, rcur * TM, sA, tid);
            asm volatile("cp.async.wait_group 0;");
            __syncthreads();
            rprev = rcur;
        }

        if (par == 0)
            tile_body(accA, accB, rowp, colp, t, istart, nIts, staleOff >= 0,
                      znb, sB, aBase, aXor, aC, bRow, bXor, bC, tid);
        else
            tile_body(accB, accA, rowp, colp, t, istart, nIts, staleOff >= 0,
                      znb, sB, aBase, aXor, aC, bRow, bXor, bC, tid);

        if (staleOff > 0)
            colp_finalize(colp, staleR, staleOff, scratch, tid, lane, warpM, warpN);
        else if (staleOff == 0)
            colp_reset(colp);

        staleOff = offcur;
        staleR = rcur;
    }

    const int parEnd = (iend - istart) & 1;
    if (parEnd == 0)
        flush_stale(accB, rowp, colp, staleOff, staleR, scratch, tid, lane, warpM, warpN);
    else
        flush_stale(accA, rowp, colp, staleOff, staleR, scratch, tid, lane, warpM, warpN);
    emit_rows(rowp, rprev, offFirst, scratch, tid, lane, warpM, warpN);
}

// ---------------------------------------------------------------------------
// 3) loss + mean (diagonal exp subtracted via g_diag)
// ---------------------------------------------------------------------------
__global__ void loss_mean_kernel(float* __restrict__ out, int B) {
    __shared__ float wsum[8];
    __shared__ unsigned int sflag;
    int lane = threadIdx.x & 31;
    int wrp = threadIdx.x >> 5;
    int rowg = blockIdx.x * 8 + wrp;
    int N = 2 * B;

    int b = rowg >> 7, lr = rowg & 127;
    float d = g_rs[(b * 33 + lane) * 128 + lr];
    if (lane == 0 && b < 32) d += g_rs[(b * 33 + 32) * 128 + lr];
    {
        int off2 = lane + 1;
        int rr = (b - off2 + 64) & 63;
        if (off2 < 32 || rr < 32) d += g_cs[(rr * 33 + off2) * 128 + lr];
    }
#pragma unroll
    for (int o = 16; o > 0; o >>= 1) d += __shfl_xor_sync(0xffffffffu, d, o);

    if (lane == 0) {
        d -= ex2f(g_diag[rowg]);              // remove self-similarity term
        float pos = g_pos[(rowg < B) ? rowg : (rowg - B)];
        wsum[wrp] = logf(d + 1e-8f) - pos;
    }
    __syncthreads();
    if (threadIdx.x == 0) {
        float s = 0.f;
#pragma unroll
        for (int i = 0; i < 8; i++) s += wsum[i];
        g_bpart[blockIdx.x] = s;
        __threadfence();
        sflag = atomicInc(&g_ctr, NLBLK - 1);
    }
    __syncthreads();
    if (sflag == NLBLK - 1) {
        __shared__ float red[256];
        int t = threadIdx.x;
        const volatile float* bp = g_bpart;
        float s = 0.f;
#pragma unroll
        for (int i = 0; i < NLBLK / 256; i++) s += bp[t + i * 256];
        red[t] = s;
        __syncthreads();
#pragma unroll
        for (int st = 128; st > 0; st >>= 1) {
            if (t < st) red[t] += red[t + st];
            __syncthreads();
        }
        if (t == 0) out[0] = red[0] / (float)N;
    }
}

// ---------------------------------------------------------------------------
extern "C" void kernel_launch(void* const* d_in, const int* in_sizes, int n_in,
                              void* d_out, int out_size) {
    const float* zi = (const float*)d_in[0];
    const float* zj = (const float*)d_in[1];
    int B = in_sizes[0] / D;  // 4096

    cudaFuncSetAttribute(denom_kernel, cudaFuncAttributeMaxDynamicSharedMemorySize, SMEM_TOTAL);

    normalize_kernel<<<B / 4, 256>>>(zi, zj, B);
    denom_kernel<<<NCTA, 256, SMEM_TOTAL>>>();
    loss_mean_kernel<<<NLBLK, 256>>>((float*)d_out, B);
}

// round 17
// speedup vs baseline: 1.0153x; 1.0153x over previous
#include <cuda_runtime.h>
#include <cuda_bf16.h>
#include <math.h>
#include <stdint.h>

// NT-Xent loss. B=4096, D=512. Symmetric fused bf16 HMMA sim-GEMM.
// R15 warp-per-pair normalize + R16 denom (uniform epilogue, diag tiles skip
// col-sum finalize) + last-block loss/mean.

#define D 512
#define MAXN 8192
#define TEMP_INV 2.0f
#define QSCALE 1.6986436f   // sqrt(2 * log2(e))
#define NCTA 148
#define NB 64
#define NTILES 2080

#define TM 128
#define KCHUNK 128

#define SA_OFF 0
#define SA_BYTES (TM * D * 2)
#define SB_OFF SA_BYTES
#define SB_BYTES (TM * KCHUNK * 2)
#define NSTAGE 3
#define SRED_OFF (SB_OFF + NSTAGE * SB_BYTES)
#define SMEM_TOTAL (SRED_OFF + 2048)

#define NLBLK 1024
#define NZR (NB * 33 * 128)

__device__ __nv_bfloat16 g_znb[(size_t)MAXN * D];
__device__ float g_pos[MAXN / 2];
__device__ float g_diag[MAXN];      // |q_row|^2 (exp2 arg of the diagonal)
__device__ float g_rs[NZR];
__device__ float g_cs[NZR];
__device__ float g_bpart[NLBLK];
__device__ unsigned int g_ctr = 0;

__device__ __forceinline__ uint32_t smem_u32(const void* p) {
    uint32_t a;
    asm("{ .reg .u64 t; cvta.to.shared.u64 t, %1; cvt.u32.u64 %0, t; }" : "=r"(a) : "l"(p));
    return a;
}
__device__ __forceinline__ float ex2f(float x) {
    float r;
    asm("ex2.approx.f32 %0, %1;" : "=f"(r) : "f"(x));
    return r;
}
__device__ __forceinline__ void ldsm4(uint32_t* r, uint32_t addr) {
    asm volatile("ldmatrix.sync.aligned.m8n8.x4.shared.b16 {%0,%1,%2,%3}, [%4];"
                 : "=r"(r[0]), "=r"(r[1]), "=r"(r[2]), "=r"(r[3]) : "r"(addr));
}
__device__ __forceinline__ void mma_bf16(float* c, const uint32_t* a, const uint32_t* b) {
    asm volatile(
        "mma.sync.aligned.m16n8k16.row.col.f32.bf16.bf16.f32 "
        "{%0,%1,%2,%3}, {%4,%5,%6,%7}, {%8,%9}, {%0,%1,%2,%3};"
        : "+f"(c[0]), "+f"(c[1]), "+f"(c[2]), "+f"(c[3])
        : "r"(a[0]), "r"(a[1]), "r"(a[2]), "r"(a[3]), "r"(b[0]), "r"(b[1]));
}
__device__ __forceinline__ void tmap(int t, int& r, int& off, int& c) {
    if (t < 32 * 33) { r = t / 33; off = t - r * 33; }
    else { int u = t - 32 * 33; r = 32 + u / 32; off = u - (u / 32) * 32; }
    c = (r + off) & 63;
}

// ---------------------------------------------------------------------------
// 1) normalize: one warp per pair (R15). Emits bf16(zn*QSCALE), positives,
//    |q|^2; zeros g_rs.
// ---------------------------------------------------------------------------
__global__ void normalize_kernel(const float* __restrict__ zi,
                                 const float* __restrict__ zj, int B) {
    int lane = threadIdx.x & 31;
    int w = threadIdx.x >> 5;
    int row = blockIdx.x * 8 + w;

    float4 vi[4], vj[4];
    const float4* pi = (const float4*)(zi + (size_t)row * D);
    const float4* pj = (const float4*)(zj + (size_t)row * D);
#pragma unroll
    for (int q = 0; q < 4; q++) { vi[q] = pi[q * 32 + lane]; vj[q] = pj[q * 32 + lane]; }

    float ssi = 0.f, ssj = 0.f, dij = 0.f;
#pragma unroll
    for (int q = 0; q < 4; q++) {
        ssi += vi[q].x * vi[q].x + vi[q].y * vi[q].y + vi[q].z * vi[q].z + vi[q].w * vi[q].w;
        ssj += vj[q].x * vj[q].x + vj[q].y * vj[q].y + vj[q].z * vj[q].z + vj[q].w * vj[q].w;
        dij += vi[q].x * vj[q].x + vi[q].y * vj[q].y + vi[q].z * vj[q].z + vi[q].w * vj[q].w;
    }
#pragma unroll
    for (int o = 16; o > 0; o >>= 1) {
        ssi += __shfl_xor_sync(0xffffffffu, ssi, o);
        ssj += __shfl_xor_sync(0xffffffffu, ssj, o);
        dij += __shfl_xor_sync(0xffffffffu, dij, o);
    }
    float ri = rsqrtf(ssi), rj = rsqrtf(ssj);
    float sci = ri * QSCALE, scj = rj * QSCALE;

    __nv_bfloat16* oi = g_znb + (size_t)row * D;
    __nv_bfloat16* oj = g_znb + (size_t)(row + B) * D;
    float qsi = 0.f, qsj = 0.f;
#pragma unroll
    for (int q = 0; q < 4; q++) {
        int e = (q * 32 + lane) * 4;
        __nv_bfloat162 a0 = __floats2bfloat162_rn(vi[q].x * sci, vi[q].y * sci);
        __nv_bfloat162 a1 = __floats2bfloat162_rn(vi[q].z * sci, vi[q].w * sci);
        *(__nv_bfloat162*)(oi + e) = a0;
        *(__nv_bfloat162*)(oi + e + 2) = a1;
        __nv_bfloat162 b0 = __floats2bfloat162_rn(vj[q].x * scj, vj[q].y * scj);
        __nv_bfloat162 b1 = __floats2bfloat162_rn(vj[q].z * scj, vj[q].w * scj);
        *(__nv_bfloat162*)(oj + e) = b0;
        *(__nv_bfloat162*)(oj + e + 2) = b1;
        float2 f;
        f = __bfloat1622float2(a0); qsi += f.x * f.x + f.y * f.y;
        f = __bfloat1622float2(a1); qsi += f.x * f.x + f.y * f.y;
        f = __bfloat1622float2(b0); qsj += f.x * f.x + f.y * f.y;
        f = __bfloat1622float2(b1); qsj += f.x * f.x + f.y * f.y;
    }
#pragma unroll
    for (int o = 16; o > 0; o >>= 1) {
        qsi += __shfl_xor_sync(0xffffffffu, qsi, o);
        qsj += __shfl_xor_sync(0xffffffffu, qsj, o);
    }
    if (lane == 0) {
        g_pos[row] = dij * ri * rj * TEMP_INV;
        g_diag[row] = qsi;
        g_diag[row + B] = qsj;
    }
    for (int i = blockIdx.x * blockDim.x + threadIdx.x; i < NZR; i += gridDim.x * blockDim.x)
        g_rs[i] = 0.0f;
}

// ---------------------------------------------------------------------------
// 2) denom helpers (R16)
// ---------------------------------------------------------------------------
__device__ __forceinline__ void prefetchB(const __nv_bfloat16* __restrict__ znb,
                                          int colBase, int kc, uint32_t smemBuf, int tid) {
#pragma unroll
    for (int i = 0; i < 8; i++) {
        int idx = tid + i * 256;
        int n = idx >> 4;
        int c = idx & 15;
        const void* g = znb + (size_t)(colBase + n) * D + kc * KCHUNK + c * 8;
        uint32_t s = smemBuf + n * 256 + ((c ^ (n & 7)) << 4);
        asm volatile("cp.async.cg.shared.global [%0], [%1], 16;" :: "r"(s), "l"(g));
    }
    asm volatile("cp.async.commit_group;");
}
__device__ __forceinline__ void loadA(const __nv_bfloat16* __restrict__ znb,
                                      int rowBase, uint32_t sA, int tid) {
#pragma unroll 8
    for (int idx = tid; idx < TM * 64; idx += 256) {
        int r = idx >> 6;
        int c = idx & 63;
        const void* g = znb + (size_t)(rowBase + r) * D + c * 8;
        uint32_t s = sA + r * 1024 + ((c ^ (r & 7)) << 4);
        asm volatile("cp.async.cg.shared.global [%0], [%1], 16;" :: "r"(s), "l"(g));
    }
    asm volatile("cp.async.commit_group;");
}

__device__ __forceinline__ void emit_rows(float rowp[2][2], int r, int offFirst,
                                          float* scratch, int tid, int lane,
                                          int warpM, int warpN) {
    __syncthreads();
#pragma unroll
    for (int mt = 0; mt < 2; mt++)
#pragma unroll
        for (int h = 0; h < 2; h++) {
            float p = rowp[mt][h];
            p += __shfl_xor_sync(0xffffffffu, p, 1);
            p += __shfl_xor_sync(0xffffffffu, p, 2);
            rowp[mt][h] = p;
        }
    if ((lane & 3) == 0) {
#pragma unroll
        for (int mt = 0; mt < 2; mt++)
#pragma unroll
            for (int h = 0; h < 2; h++) {
                int rl = warpM * 32 + mt * 16 + (lane >> 2) + 8 * h;
                scratch[rl * 2 + warpN] = rowp[mt][h];
            }
    }
    __syncthreads();
    if (tid < TM)
        g_rs[(r * 33 + offFirst) * 128 + tid] = scratch[tid * 2] + scratch[tid * 2 + 1];
}

__device__ __forceinline__ void stale_groups(int g0, float (&st)[2][8][4],
                                             float (&rowp)[2][2], float (&colp)[8][2]) {
#pragma unroll
    for (int u = 0; u < 4; u++) {
        const int g = g0 + u;
        const int mt = g >> 3, nt = g & 7;
        float e0 = ex2f(st[mt][nt][0]);
        float e1 = ex2f(st[mt][nt][1]);
        float e2 = ex2f(st[mt][nt][2]);
        float e3 = ex2f(st[mt][nt][3]);
        rowp[mt][0] += e0 + e1;
        rowp[mt][1] += e2 + e3;
        colp[nt][0] += e0 + e2;
        colp[nt][1] += e1 + e3;
        st[mt][nt][0] = 0.f; st[mt][nt][1] = 0.f;
        st[mt][nt][2] = 0.f; st[mt][nt][3] = 0.f;
    }
}

__device__ __forceinline__ void colp_reset(float (&colp)[8][2]) {
#pragma unroll
    for (int nt = 0; nt < 8; nt++) { colp[nt][0] = 0.f; colp[nt][1] = 0.f; }
}

__device__ __forceinline__ void colp_finalize(float (&colp)[8][2], int staleR, int staleOff,
                                              float* scratch, int tid, int lane,
                                              int warpM, int warpN) {
    __syncthreads();
#pragma unroll
    for (int nt = 0; nt < 8; nt++)
#pragma unroll
        for (int q = 0; q < 2; q++) {
            float p = colp[nt][q];
            p += __shfl_xor_sync(0xffffffffu, p, 4);
            p += __shfl_xor_sync(0xffffffffu, p, 8);
            p += __shfl_xor_sync(0xffffffffu, p, 16);
            colp[nt][q] = p;
        }
    if (lane < 4) {
#pragma unroll
        for (int nt = 0; nt < 8; nt++)
#pragma unroll
            for (int q = 0; q < 2; q++)
                scratch[(warpN * 4 + warpM) * 64 + nt * 8 + lane * 2 + q] = colp[nt][q];
    }
    __syncthreads();
    if (tid < TM) {
        int wn = tid >> 6, cl = tid & 63;
        float s = scratch[(wn * 4 + 0) * 64 + cl] + scratch[(wn * 4 + 1) * 64 + cl]
                + scratch[(wn * 4 + 2) * 64 + cl] + scratch[(wn * 4 + 3) * 64 + cl];
        g_cs[(staleR * 33 + staleOff) * 128 + tid] = s;
    }
    colp_reset(colp);
}

__device__ __forceinline__ void flush_stale(float (&st)[2][8][4], float (&rowp)[2][2],
                                            float (&colp)[8][2], int staleOff, int staleR,
                                            float* scratch, int tid, int lane,
                                            int warpM, int warpN) {
    stale_groups(0, st, rowp, colp);
    stale_groups(4, st, rowp, colp);
    stale_groups(8, st, rowp, colp);
    stale_groups(12, st, rowp, colp);
    if (staleOff > 0)
        colp_finalize(colp, staleR, staleOff, scratch, tid, lane, warpM, warpN);
    else
        colp_reset(colp);   // diag tile col sums unused
}

__device__ __forceinline__ void tile_body(
    float (&cur)[2][8][4], float (&st)[2][8][4],
    float (&rowp)[2][2], float (&colp)[8][2],
    int tIdx, int istart, int nIts, int haveStale,
    const __nv_bfloat16* __restrict__ znb,
    uint32_t sB, uint32_t aBase, int aXor, int aC,
    int bRow, int bXor, int bC, int tid)
{
#pragma unroll
    for (int kc = 0; kc < 4; ++kc) {
        const int git = (tIdx - istart) * 4 + kc;
        asm volatile("cp.async.wait_group 1;");
        __syncthreads();
        if (git + 2 < nIts) {
            int r2, o2, c2;
            tmap(istart + ((git + 2) >> 2), r2, o2, c2);
            prefetchB(znb, c2 * TM, (git + 2) & 3, sB + ((git + 2) % 3) * SB_BYTES, tid);
        } else {
            asm volatile("cp.async.commit_group;");
        }
        const uint32_t bufB = sB + (git % 3) * SB_BYTES;
#pragma unroll
        for (int s = 0; s < 8; ++s) {
            uint32_t af[2][4];
#pragma unroll
            for (int mt = 0; mt < 2; mt++)
                ldsm4(af[mt], aBase + mt * 16384 + (((kc * 16 + s * 2 + aC) ^ aXor) << 4));
#pragma unroll
            for (int bg = 0; bg < 4; bg++) {
                uint32_t bf[4];
                ldsm4(bf, bufB + (bRow + bg * 16) * 256 + (((s * 2 + bC) ^ bXor) << 4));
#pragma unroll
                for (int mt = 0; mt < 2; mt++) {
                    mma_bf16(cur[mt][bg * 2], af[mt], bf);
                    mma_bf16(cur[mt][bg * 2 + 1], af[mt], bf + 2);
                }
            }
        }
        if (haveStale)
            stale_groups(kc * 4, st, rowp, colp);
    }
}

__global__ void __launch_bounds__(256, 1) denom_kernel() {
    extern __shared__ char smem[];
    const int tid = threadIdx.x;
    const int lane = tid & 31;
    const int wid = tid >> 5;
    const int warpM = wid & 3;
    const int warpN = wid >> 2;
    const int cta = blockIdx.x;

    const __nv_bfloat16* __restrict__ znb = g_znb;
    uint32_t sA = smem_u32(smem) + SA_OFF;
    uint32_t sB = smem_u32(smem) + SB_OFF;
    float* scratch = (float*)(smem + SRED_OFF);

    const int aRow = warpM * 32 + (lane & 15);
    const uint32_t aBase = sA + aRow * 1024;
    const int aXor = aRow & 7;
    const int aC = lane >> 4;
    const int bRow = warpN * 64 + (lane & 7) + ((lane >> 4) << 3);
    const int bXor = bRow & 7;
    const int bC = (lane >> 3) & 1;

    const int istart = (cta * NTILES) / NCTA;
    const int iend = ((cta + 1) * NTILES) / NCTA;
    const int nIts = (iend - istart) * 4;

    int rcur, offcur, ccur;
    tmap(istart, rcur, offcur, ccur);
    int rprev = rcur;
    int offFirst = offcur;

    loadA(znb, rcur * TM, sA, tid);
    asm volatile("cp.async.wait_group 0;");
    __syncthreads();
    prefetchB(znb, ccur * TM, 0, sB, tid);
    prefetchB(znb, ccur * TM, 1, sB + SB_BYTES, tid);

    float accA[2][8][4], accB[2][8][4];
#pragma unroll
    for (int mt = 0; mt < 2; mt++)
#pragma unroll
        for (int nt = 0; nt < 8; nt++)
#pragma unroll
            for (int j = 0; j < 4; j++) { accA[mt][nt][j] = 0.f; accB[mt][nt][j] = 0.f; }
    float rowp[2][2] = {{0.f, 0.f}, {0.f, 0.f}};
    float colp[8][2];
    colp_reset(colp);

    int staleOff = -1, staleR = 0;

    for (int t = istart; t < iend; ++t) {
        tmap(t, rcur, offcur, ccur);
        const int par = (t - istart) & 1;
        if (rcur != rprev) {
            if (staleOff >= 0) {
                if (par == 0)
                    flush_stale(accB, rowp, colp, staleOff, staleR, scratch, tid, lane, warpM, warpN);
                else
                    flush_stale(accA, rowp, colp, staleOff, staleR, scratch, tid, lane, warpM, warpN);
                staleOff = -1;
            }
            emit_rows(rowp, rprev, offFirst, scratch, tid, lane, warpM, warpN);
            rowp[0][0] = rowp[0][1] = rowp[1][0] = rowp[1][1] = 0.f;
            offFirst = offcur;
            asm volatile("cp.async.wait_group 0;");
            __syncthreads();
            loadA(znb, rcur * TM, sA, tid);
            asm volatile("cp.async.wait_group 0;");
            __syncthreads();
            rprev = rcur;
        }

        if (par == 0)
            tile_body(accA, accB, rowp, colp, t, istart, nIts, staleOff >= 0,
                      znb, sB, aBase, aXor, aC, bRow, bXor, bC, tid);
        else
            tile_body(accB, accA, rowp, colp, t, istart, nIts, staleOff >= 0,
                      znb, sB, aBase, aXor, aC, bRow, bXor, bC, tid);

        if (staleOff > 0)
            colp_finalize(colp, staleR, staleOff, scratch, tid, lane, warpM, warpN);
        else if (staleOff == 0)
            colp_reset(colp);

        staleOff = offcur;
        staleR = rcur;
    }

    const int parEnd = (iend - istart) & 1;
    if (parEnd == 0)
        flush_stale(accB, rowp, colp, staleOff, staleR, scratch, tid, lane, warpM, warpN);
    else
        flush_stale(accA, rowp, colp, staleOff, staleR, scratch, tid, lane, warpM, warpN);
    emit_rows(rowp, rprev, offFirst, scratch, tid, lane, warpM, warpN);
}

// ---------------------------------------------------------------------------
// 3) loss + mean (diagonal exp subtracted via g_diag)
// ---------------------------------------------------------------------------
__global__ void loss_mean_kernel(float* __restrict__ out, int B) {
    __shared__ float wsum[8];
    __shared__ unsigned int sflag;
    int lane = threadIdx.x & 31;
    int wrp = threadIdx.x >> 5;
    int rowg = blockIdx.x * 8 + wrp;
    int N = 2 * B;

    int b = rowg >> 7, lr = rowg & 127;
    float d = g_rs[(b * 33 + lane) * 128 + lr];
    if (lane == 0 && b < 32) d += g_rs[(b * 33 + 32) * 128 + lr];
    {
        int off2 = lane + 1;
        int rr = (b - off2 + 64) & 63;
        if (off2 < 32 || rr < 32) d += g_cs[(rr * 33 + off2) * 128 + lr];
    }
#pragma unroll
    for (int o = 16; o > 0; o >>= 1) d += __shfl_xor_sync(0xffffffffu, d, o);

    if (lane == 0) {
        d -= ex2f(g_diag[rowg]);              // remove self-similarity term
        float pos = g_pos[(rowg < B) ? rowg : (rowg - B)];
        wsum[wrp] = logf(d + 1e-8f) - pos;
    }
    __syncthreads();
    if (threadIdx.x == 0) {
        float s = 0.f;
#pragma unroll
        for (int i = 0; i < 8; i++) s += wsum[i];
        g_bpart[blockIdx.x] = s;
        __threadfence();
        sflag = atomicInc(&g_ctr, NLBLK - 1);
    }
    __syncthreads();
    if (sflag == NLBLK - 1) {
        __shared__ float red[256];
        int t = threadIdx.x;
        const volatile float* bp = g_bpart;
        float s = 0.f;
#pragma unroll
        for (int i = 0; i < NLBLK / 256; i++) s += bp[t + i * 256];
        red[t] = s;
        __syncthreads();
#pragma unroll
        for (int st = 128; st > 0; st >>= 1) {
            if (t < st) red[t] += red[t + st];
            __syncthreads();
        }
        if (t == 0) out[0] = red[0] / (float)N;
    }
}

// ---------------------------------------------------------------------------
extern "C" void kernel_launch(void* const* d_in, const int* in_sizes, int n_in,
                              void* d_out, int out_size) {
    const float* zi = (const float*)d_in[0];
    const float* zj = (const float*)d_in[1];
    int B = in_sizes[0] / D;  // 4096

    cudaFuncSetAttribute(denom_kernel, cudaFuncAttributeMaxDynamicSharedMemorySize, SMEM_TOTAL);

    normalize_kernel<<<B / 8, 256>>>(zi, zj, B);
    denom_kernel<<<NCTA, 256, SMEM_TOTAL>>>();
    loss_mean_kernel<<<NLBLK, 256>>>((float*)d_out, B);
}